// round 10
// baseline (speedup 1.0000x reference)
#include <cuda_runtime.h>
#include <cstdint>

// Inverse 2D DWT, single level. (4,64,256,256) f32 x4 subbands -> (4,64,512,512) f32.
// Producer/consumer: one block owns (plane, 64-row chunk). A single elected thread
// streams input rows via cp.async.bulk (4KB per subband per 4-row stage) into a
// 5-deep smem ring (~80KB in flight), paced by mbarrier full/empty pairs.
// H-reflection rows (r0-1, r0+64) are staged separately (P/Q) with reflection baked
// into the producer's source addresses. Consumers run the validated warp-autonomous
// core: each warp owns a 64-col strip, each lane 2 cols, rolling 3-row register
// window read from smem, f32x2 FFMA math, shuffle-based row pass, float4 stores.
// One mbarrier wait + arrive per 4 rows; no __syncthreads in the main loop.

#define HH 256
#define WW 256
#define RB 64            // rows per block
#define NT 128
#define DEPTH 5          // ring depth (stages in flight)
#define NSTAGE 16        // 4-row stages per block
#define STG_FLOATS 4096  // 4 subbands * 4 rows * 256
#define SUB_STRIDE 1024  // floats between subbands within a stage (4*256)
#define ROW_FLOATS 256

typedef unsigned long long u64;

__device__ __forceinline__ u64 pk(float lo, float hi) {
    u64 r; asm("mov.b64 %0, {%1, %2};" : "=l"(r) : "f"(lo), "f"(hi)); return r;
}
__device__ __forceinline__ void unpk(u64 v, float& lo, float& hi) {
    asm("mov.b64 {%0, %1}, %2;" : "=f"(lo), "=f"(hi) : "l"(v));
}
__device__ __forceinline__ float lof(u64 v) { float a, b; unpk(v, a, b); return a; }
__device__ __forceinline__ float hif(u64 v) { float a, b; unpk(v, a, b); return b; }
__device__ __forceinline__ u64 ffma2(u64 a, u64 b, u64 c) {
    u64 d; asm("fma.rn.f32x2 %0, %1, %2, %3;" : "=l"(d) : "l"(a), "l"(b), "l"(c)); return d;
}
__device__ __forceinline__ u64 fmul2(u64 a, u64 b) {
    u64 d; asm("mul.rn.f32x2 %0, %1, %2;" : "=l"(d) : "l"(a), "l"(b)); return d;
}
__device__ __forceinline__ int reflH(int i) {
    return i < 0 ? -i : (i >= HH ? 2 * HH - 2 - i : i);
}
__device__ __forceinline__ float shup(float v) { return __shfl_up_sync(0xffffffffu, v, 1); }
__device__ __forceinline__ float shdn(float v) { return __shfl_down_sync(0xffffffffu, v, 1); }

__device__ __forceinline__ void mbar_init(uint32_t a, uint32_t cnt) {
    asm volatile("mbarrier.init.shared.b64 [%0], %1;" :: "r"(a), "r"(cnt) : "memory");
}
__device__ __forceinline__ void mbar_arrive(uint32_t a) {
    asm volatile("mbarrier.arrive.shared.b64 _, [%0];" :: "r"(a) : "memory");
}
__device__ __forceinline__ void mbar_expect(uint32_t a, uint32_t tx) {
    asm volatile("mbarrier.arrive.expect_tx.shared.b64 _, [%0], %1;"
                 :: "r"(a), "r"(tx) : "memory");
}
__device__ __forceinline__ void mbar_wait(uint32_t a, uint32_t ph) {
    asm volatile(
        "{\n\t.reg .pred P;\n\t"
        "WL_%=:\n\t"
        "mbarrier.try_wait.parity.acquire.cta.shared::cta.b64 P, [%0], %1, 0x989680;\n\t"
        "@P bra.uni WD_%=;\n\t"
        "bra.uni WL_%=;\n\t"
        "WD_%=:\n\t}"
        :: "r"(a), "r"(ph) : "memory");
}
__device__ __forceinline__ void bulk_cp(uint32_t dst, const float* src,
                                        uint32_t bytes, uint32_t mbar) {
    asm volatile(
        "cp.async.bulk.shared::cta.global.mbarrier::complete_tx::bytes [%0], [%1], %2, [%3];"
        :: "r"(dst), "l"(src), "r"(bytes), "r"(mbar) : "memory");
}

__global__ __launch_bounds__(NT)
void idwt2d(const float* __restrict__ ss, const float* __restrict__ sd,
            const float* __restrict__ ds, const float* __restrict__ dd,
            const float* __restrict__ hf, const float* __restrict__ gf,
            float* __restrict__ out)
{
    extern __shared__ float smem[];
    __shared__ u64 mbar[2 * DEPTH];   // [0..4]=full, [5..9]=empty

    float* ring = smem;                          // DEPTH * STG_FLOATS
    float* Pb   = smem + DEPTH * STG_FLOATS;     // 4 * 256 (row reflH(r0-1))
    float* Qb   = Pb + 4 * ROW_FLOATS;           // 4 * 256 (row reflH(r0+RB))

    const int tid  = threadIdx.x;
    const int lane = tid & 31;
    const int wid  = tid >> 5;
    const int bc   = blockIdx.z;
    const int r0   = blockIdx.y * RB;
    const int wb   = 64 * wid;
    const int c    = wb + 2 * lane;
    const int hcol = (lane == 31) ? ((wb + 64 < WW) ? wb + 64 : WW - 2)
                                  : ((wb > 0) ? wb - 1 : 1);

    const size_t base = (size_t)bc * (HH * WW);
    const float* gin0 = ss + base;
    const float* gin1 = sd + base;
    const float* gin2 = ds + base;
    const float* gin3 = dd + base;
    float* __restrict__ pout = out + (size_t)bc * (4 * HH * WW) + 2 * c;

    const uint32_t mb0    = (uint32_t)__cvta_generic_to_shared(&mbar[0]);
    const uint32_t ring0  = (uint32_t)__cvta_generic_to_shared(ring);
    const uint32_t Pb0    = (uint32_t)__cvta_generic_to_shared(Pb);
    const uint32_t Qb0    = (uint32_t)__cvta_generic_to_shared(Qb);

    if (tid == 0) {
        #pragma unroll
        for (int k = 0; k < DEPTH; ++k) {
            mbar_init(mb0 + 8u * k, 1);             // full: producer's expect_tx arrive
            mbar_init(mb0 + 8u * (DEPTH + k), NT);  // empty: all threads arrive
        }
    }
    __syncthreads();

    // ---- producer priming: stages 0..4 (+ P with stage 0) ----
    if (tid == 0) {
        asm volatile("fence.proxy.async.shared::cta;" ::: "memory");
        const int rp = reflH(r0 - 1);
        // stage 0 + P share full[0]
        mbar_expect(mb0, 4u * 4096u + 4u * 1024u);
        bulk_cp(ring0 + 0u * 4096u * 4u /*bytes*/, gin0 + (size_t)r0 * WW, 16384u / 4u * 0 + 4096u, mb0);
        bulk_cp(ring0 + 1u * SUB_STRIDE * 4u,      gin1 + (size_t)r0 * WW, 4096u, mb0);
        bulk_cp(ring0 + 2u * SUB_STRIDE * 4u,      gin2 + (size_t)r0 * WW, 4096u, mb0);
        bulk_cp(ring0 + 3u * SUB_STRIDE * 4u,      gin3 + (size_t)r0 * WW, 4096u, mb0);
        bulk_cp(Pb0 + 0u * 1024u, gin0 + (size_t)rp * WW, 1024u, mb0);
        bulk_cp(Pb0 + 1u * 1024u, gin1 + (size_t)rp * WW, 1024u, mb0);
        bulk_cp(Pb0 + 2u * 1024u, gin2 + (size_t)rp * WW, 1024u, mb0);
        bulk_cp(Pb0 + 3u * 1024u, gin3 + (size_t)rp * WW, 1024u, mb0);
        #pragma unroll
        for (int s = 1; s < DEPTH; ++s) {
            const uint32_t fbar = mb0 + 8u * s;
            const uint32_t sbase = ring0 + (uint32_t)(s * STG_FLOATS) * 4u;
            mbar_expect(fbar, 4u * 4096u);
            bulk_cp(sbase + 0u * SUB_STRIDE * 4u, gin0 + (size_t)(r0 + 4 * s) * WW, 4096u, fbar);
            bulk_cp(sbase + 1u * SUB_STRIDE * 4u, gin1 + (size_t)(r0 + 4 * s) * WW, 4096u, fbar);
            bulk_cp(sbase + 2u * SUB_STRIDE * 4u, gin2 + (size_t)(r0 + 4 * s) * WW, 4096u, fbar);
            bulk_cp(sbase + 3u * SUB_STRIDE * 4u, gin3 + (size_t)(r0 + 4 * s) * WW, 4096u, fbar);
        }
    }

    // ---- packed coefficients ----
    u64 H0, H1, H2, H3, H4, H5, G0, G1, G2, G3, G4, G5;
    {
        const float a0 = hf[0], a1 = hf[1], a2 = hf[2], a3 = hf[3], a4 = hf[4], a5 = hf[5];
        const float b0 = gf[0], b1 = gf[1], b2 = gf[2], b3 = gf[3], b4 = gf[4], b5 = gf[5];
        H0 = pk(a0, a0); H1 = pk(a1, a1); H2 = pk(a2, a2);
        H3 = pk(a3, a3); H4 = pk(a4, a4); H5 = pk(a5, a5);
        G0 = pk(b0, b0); G1 = pk(b1, b1); G2 = pk(b2, b2);
        G3 = pk(b3, b3); G4 = pk(b4, b4); G5 = pk(b5, b5);
    }

    // ---- consumer: wait stage 0 (covers P), prime window rows j=0 (P), j=1 ----
    int s_waited = 0;
    mbar_wait(mb0, 0);

    u64 S0, S1, S2, T0, T1, T2, U0, U1, U2, V0, V1, V2;
    float hs0, hs1, hs2, ht0, ht1, ht2, hu0, hu1, hu2, hv0, hv1, hv2;
    {
        // j = 0 -> P (subband stride 256)
        S0 = *(const u64*)(Pb + c);                    hs0 = Pb[hcol];
        T0 = *(const u64*)(Pb + ROW_FLOATS + c);       ht0 = Pb[ROW_FLOATS + hcol];
        U0 = *(const u64*)(Pb + 2 * ROW_FLOATS + c);   hu0 = Pb[2 * ROW_FLOATS + hcol];
        V0 = *(const u64*)(Pb + 3 * ROW_FLOATS + c);   hv0 = Pb[3 * ROW_FLOATS + hcol];
        // j = 1 -> stage 0 row 0 (subband stride 1024)
        const float* rb = ring;
        S1 = *(const u64*)(rb + c);                    hs1 = rb[hcol];
        T1 = *(const u64*)(rb + SUB_STRIDE + c);       ht1 = rb[SUB_STRIDE + hcol];
        U1 = *(const u64*)(rb + 2 * SUB_STRIDE + c);   hu1 = rb[2 * SUB_STRIDE + hcol];
        V1 = *(const u64*)(rb + 3 * SUB_STRIDE + c);   hv1 = rb[3 * SUB_STRIDE + hcol];
    }

    #pragma unroll 4
    for (int i = 0; i < RB; ++i) {
        const int j = i + 2;                       // new window row
        const int s_needed = (j >= 65) ? (NSTAGE - 1) : ((j - 1) >> 2);
        while (s_waited < s_needed) {
            ++s_waited;
            mbar_wait(mb0 + 8u * (s_waited % DEPTH), (s_waited / DEPTH) & 1);
        }

        // read row j from smem
        const float* rb; int sstr;
        if (j == 65) { rb = Qb; sstr = ROW_FLOATS; }
        else {
            const int jm = j - 1;
            rb = ring + ((jm >> 2) % DEPTH) * STG_FLOATS + (jm & 3) * ROW_FLOATS;
            sstr = SUB_STRIDE;
        }
        S2 = *(const u64*)(rb + c);            hs2 = rb[hcol];
        T2 = *(const u64*)(rb + sstr + c);     ht2 = rb[sstr + hcol];
        U2 = *(const u64*)(rb + 2 * sstr + c); hu2 = rb[2 * sstr + hcol];
        V2 = *(const u64*)(rb + 3 * sstr + c); hv2 = rb[3 * sstr + hcol];

        // ---- column pass (f32x2, both owned columns) ----
        const u64 A0 = ffma2(H4, S0, ffma2(H2, S1, ffma2(H0, S2,
                       ffma2(G4, T0, ffma2(G2, T1, fmul2(G0, T2))))));
        const u64 A1 = ffma2(H5, S0, ffma2(H3, S1, ffma2(H1, S2,
                       ffma2(G5, T0, ffma2(G3, T1, fmul2(G1, T2))))));
        const u64 A2 = ffma2(H4, U0, ffma2(H2, U1, ffma2(H0, U2,
                       ffma2(G4, V0, ffma2(G2, V1, fmul2(G0, V2))))));
        const u64 A3 = ffma2(H5, U0, ffma2(H3, U1, ffma2(H1, U2,
                       ffma2(G5, V0, ffma2(G3, V1, fmul2(G1, V2))))));

        // ---- halo column pass (packed pairwise: lo = s-side, hi = d-side) ----
        const u64 P0 = pk(hs0, hu0), Q0 = pk(ht0, hv0);
        const u64 P1 = pk(hs1, hu1), Q1 = pk(ht1, hv1);
        const u64 P2 = pk(hs2, hu2), Q2 = pk(ht2, hv2);
        const u64 B02 = ffma2(H4, P0, ffma2(H2, P1, ffma2(H0, P2,
                        ffma2(G4, Q0, ffma2(G2, Q1, fmul2(G0, Q2))))));  // (b0,b2)
        const u64 B13 = ffma2(H5, P0, ffma2(H3, P1, ffma2(H1, P2,
                        ffma2(G5, Q0, ffma2(G3, Q1, fmul2(G1, Q2))))));  // (b1,b3)

        // ---- row pass + stores ----
        const int r = r0 + i;
        #pragma unroll
        for (int py = 0; py < 2; ++py) {
            const u64 X = py ? A1 : A0;
            const u64 Y = py ? A3 : A2;
            const u64 B = py ? B13 : B02;
            const float hx = lof(B), hy = hif(B);

            float xm = shup(hif(X)); if (lane == 0)  xm = hx;   // v[c-1]
            float xp = shdn(lof(X)); if (lane == 31) xp = hx;   // v[c+2]
            float ym = shup(hif(Y)); if (lane == 0)  ym = hy;
            float yp = shdn(lof(Y)); if (lane == 31) yp = hy;

            const u64 AX = pk(xm, lof(X)), CX = pk(hif(X), xp);
            const u64 AY = pk(ym, lof(Y)), CY = pk(hif(Y), yp);

            const u64 pe = ffma2(H4, AX, ffma2(H2, X, ffma2(H0, CX,
                           ffma2(G4, AY, ffma2(G2, Y, fmul2(G0, CY))))));
            const u64 po = ffma2(H5, AX, ffma2(H3, X, ffma2(H1, CX,
                           ffma2(G5, AY, ffma2(G3, Y, fmul2(G1, CY))))));

            float e0, e1, f0, f1;
            unpk(pe, e0, e1); unpk(po, f0, f1);
            __stcs((float4*)(pout + (size_t)(2 * r + py) * (2 * WW)),
                   make_float4(e0, f0, e1, f1));
        }

        // ---- roll window ----
        S0 = S1; S1 = S2; T0 = T1; T1 = T2;
        U0 = U1; U1 = U2; V0 = V1; V1 = V2;
        hs0 = hs1; hs1 = hs2; ht0 = ht1; ht1 = ht2;
        hu0 = hu1; hu1 = hu2; hv0 = hv1; hv1 = hv2;

        // ---- free stage / refill ring ----
        if ((i & 3) == 2) {
            const int s_free = (i - 2) >> 2;                 // 0..15
            mbar_arrive(mb0 + 8u * (DEPTH + (s_free % DEPTH)));
            if (tid == 0) {
                const int s_new = s_free + DEPTH;            // 5..20
                if (s_new < NSTAGE) {
                    mbar_wait(mb0 + 8u * (DEPTH + (s_new % DEPTH)),
                              ((s_new - DEPTH) / DEPTH) & 1);
                    const uint32_t fbar = mb0 + 8u * (s_new % DEPTH);
                    const bool last = (s_new == NSTAGE - 1);
                    mbar_expect(fbar, 4u * 4096u + (last ? 4u * 1024u : 0u));
                    const uint32_t sbase = ring0 + (uint32_t)((s_new % DEPTH) * STG_FLOATS) * 4u;
                    const size_t gr = (size_t)(r0 + 4 * s_new) * WW;
                    bulk_cp(sbase + 0u * SUB_STRIDE * 4u, gin0 + gr, 4096u, fbar);
                    bulk_cp(sbase + 1u * SUB_STRIDE * 4u, gin1 + gr, 4096u, fbar);
                    bulk_cp(sbase + 2u * SUB_STRIDE * 4u, gin2 + gr, 4096u, fbar);
                    bulk_cp(sbase + 3u * SUB_STRIDE * 4u, gin3 + gr, 4096u, fbar);
                    if (last) {
                        const int rq = reflH(r0 + RB);
                        bulk_cp(Qb0 + 0u * 1024u, gin0 + (size_t)rq * WW, 1024u, fbar);
                        bulk_cp(Qb0 + 1u * 1024u, gin1 + (size_t)rq * WW, 1024u, fbar);
                        bulk_cp(Qb0 + 2u * 1024u, gin2 + (size_t)rq * WW, 1024u, fbar);
                        bulk_cp(Qb0 + 3u * 1024u, gin3 + (size_t)rq * WW, 1024u, fbar);
                    }
                }
            }
        }
    }
}

extern "C" void kernel_launch(void* const* d_in, const int* in_sizes, int n_in,
                              void* d_out, int out_size) {
    const float* ss = (const float*)d_in[0];
    const float* sd = (const float*)d_in[1];
    const float* ds = (const float*)d_in[2];
    const float* dd = (const float*)d_in[3];
    const float* h  = (const float*)d_in[4];
    const float* g  = (const float*)d_in[5];
    float* out = (float*)d_out;

    const int smem_bytes = (DEPTH * STG_FLOATS + 8 * ROW_FLOATS) * 4;  // 90112
    static bool attr_set = false;
    if (!attr_set) {
        cudaFuncSetAttribute(idwt2d, cudaFuncAttributeMaxDynamicSharedMemorySize, smem_bytes);
        attr_set = true;
    }

    dim3 grid(1, HH / RB, 4 * 64);   // (1, 4, 256) = 1024 blocks
    idwt2d<<<grid, NT, smem_bytes>>>(ss, sd, ds, dd, h, g, out);
}

// round 11
// speedup vs baseline: 1.6958x; 1.6958x over previous
#include <cuda_runtime.h>

// Inverse 2D DWT, single level. (4,64,256,256) f32 x4 subbands -> (4,64,512,512) f32.
// Warp-autonomous, LDG.128, long-stream edition: one warp owns a 128-col strip x 64
// rows (each lane 4 adjacent columns = one ulonglong2 per subband-row).
//  - Grid = 1024 blocks x 2 warps, 8 blocks/SM -> exactly ONE wave on 152 SMs.
//  - Rolling 3-row window; next row loaded right after the column pass.
//  - W-edge reflection in-lane; one interior halo column per strip (scalar loads).
//  - All math packed fp32x2 (FFMA2); shuffle row pass; float4 streaming stores.

#define HH 256
#define WW 256
#define RW 64
#define NT 64

typedef unsigned long long u64;

__device__ __forceinline__ u64 pk(float lo, float hi) {
    u64 r; asm("mov.b64 %0, {%1, %2};" : "=l"(r) : "f"(lo), "f"(hi)); return r;
}
__device__ __forceinline__ void unpk(u64 v, float& lo, float& hi) {
    asm("mov.b64 {%0, %1}, %2;" : "=f"(lo), "=f"(hi) : "l"(v));
}
__device__ __forceinline__ float lof(u64 v) { float a, b; unpk(v, a, b); return a; }
__device__ __forceinline__ float hif(u64 v) { float a, b; unpk(v, a, b); return b; }
__device__ __forceinline__ u64 ffma2(u64 a, u64 b, u64 c) {
    u64 d; asm("fma.rn.f32x2 %0, %1, %2, %3;" : "=l"(d) : "l"(a), "l"(b), "l"(c)); return d;
}
__device__ __forceinline__ u64 fmul2(u64 a, u64 b) {
    u64 d; asm("mul.rn.f32x2 %0, %1, %2;" : "=l"(d) : "l"(a), "l"(b)); return d;
}
__device__ __forceinline__ int reflH(int i) {
    return i < 0 ? -i : (i >= HH ? 2 * HH - 2 - i : i);
}
__device__ __forceinline__ float shup(float v) { return __shfl_up_sync(0xffffffffu, v, 1); }
__device__ __forceinline__ float shdn(float v) { return __shfl_down_sync(0xffffffffu, v, 1); }
__device__ __forceinline__ ulonglong2 ldg4(const float* __restrict__ p, int row) {
    return __ldcs((const ulonglong2*)(p + (size_t)row * WW));
}
__device__ __forceinline__ float ldg1(const float* __restrict__ p, int row, int dq) {
    return __ldcs(p + (size_t)row * WW + dq);
}

__global__ __launch_bounds__(NT, 8)
void idwt2d(const float* __restrict__ ss, const float* __restrict__ sd,
            const float* __restrict__ ds, const float* __restrict__ dd,
            const float* __restrict__ hf, const float* __restrict__ gf,
            float* __restrict__ out)
{
    const int lane  = threadIdx.x & 31;
    const int strip = threadIdx.x >> 5;               // 0: cols 0-127, 1: cols 128-255
    const int bc    = blockIdx.z;
    const int r0    = blockIdx.y * RW;
    const int c     = strip * 128 + 4 * lane;         // first of 4 owned columns
    const int dq    = (strip ? 127 : 128) - c;        // interior halo column offset

    const size_t base = (size_t)bc * (HH * WW);
    const float* __restrict__ pss = ss + base + c;
    const float* __restrict__ psd = sd + base + c;
    const float* __restrict__ pds = ds + base + c;
    const float* __restrict__ pdd = dd + base + c;
    float* __restrict__ pout = out + (size_t)bc * (4 * HH * WW) + 2 * c;

    u64 H0, H1, H2, H3, H4, H5, G0, G1, G2, G3, G4, G5;
    {
        const float a0 = hf[0], a1 = hf[1], a2 = hf[2], a3 = hf[3], a4 = hf[4], a5 = hf[5];
        const float b0 = gf[0], b1 = gf[1], b2 = gf[2], b3 = gf[3], b4 = gf[4], b5 = gf[5];
        H0 = pk(a0, a0); H1 = pk(a1, a1); H2 = pk(a2, a2);
        H3 = pk(a3, a3); H4 = pk(a4, a4); H5 = pk(a5, a5);
        G0 = pk(b0, b0); G1 = pk(b1, b1); G2 = pk(b2, b2);
        G3 = pk(b3, b3); G4 = pk(b4, b4); G5 = pk(b5, b5);
    }

    // 3-row window: a = row r-1, b = row r, c-slot = row r+1
    ulonglong2 Sa, Sb, Sc, Ta, Tb, Tc, Ua, Ub, Uc, Va, Vb, Vc;
    float hsa, hsb, hsc, hta, htb, htc, hua, hub, huc, hva, hvb, hvc;
    {
        const int rm = reflH(r0 - 1);
        Sa = ldg4(pss, rm); Ta = ldg4(psd, rm); Ua = ldg4(pds, rm); Va = ldg4(pdd, rm);
        hsa = ldg1(pss, rm, dq); hta = ldg1(psd, rm, dq);
        hua = ldg1(pds, rm, dq); hva = ldg1(pdd, rm, dq);
        Sb = ldg4(pss, r0); Tb = ldg4(psd, r0); Ub = ldg4(pds, r0); Vb = ldg4(pdd, r0);
        hsb = ldg1(pss, r0, dq); htb = ldg1(psd, r0, dq);
        hub = ldg1(pds, r0, dq); hvb = ldg1(pdd, r0, dq);
        Sc = ldg4(pss, r0 + 1); Tc = ldg4(psd, r0 + 1); Uc = ldg4(pds, r0 + 1); Vc = ldg4(pdd, r0 + 1);
        hsc = ldg1(pss, r0 + 1, dq); htc = ldg1(psd, r0 + 1, dq);
        huc = ldg1(pds, r0 + 1, dq); hvc = ldg1(pdd, r0 + 1, dq);
    }

    #pragma unroll 8
    for (int i = 0; i < RW; ++i) {
        const int r = r0 + i;

        // ---- column pass (4 arrays x 2 u64 halves) ----
        const u64 A0x = ffma2(H4, Sa.x, ffma2(H2, Sb.x, ffma2(H0, Sc.x,
                        ffma2(G4, Ta.x, ffma2(G2, Tb.x, fmul2(G0, Tc.x))))));
        const u64 A0y = ffma2(H4, Sa.y, ffma2(H2, Sb.y, ffma2(H0, Sc.y,
                        ffma2(G4, Ta.y, ffma2(G2, Tb.y, fmul2(G0, Tc.y))))));
        const u64 A1x = ffma2(H5, Sa.x, ffma2(H3, Sb.x, ffma2(H1, Sc.x,
                        ffma2(G5, Ta.x, ffma2(G3, Tb.x, fmul2(G1, Tc.x))))));
        const u64 A1y = ffma2(H5, Sa.y, ffma2(H3, Sb.y, ffma2(H1, Sc.y,
                        ffma2(G5, Ta.y, ffma2(G3, Tb.y, fmul2(G1, Tc.y))))));
        const u64 A2x = ffma2(H4, Ua.x, ffma2(H2, Ub.x, ffma2(H0, Uc.x,
                        ffma2(G4, Va.x, ffma2(G2, Vb.x, fmul2(G0, Vc.x))))));
        const u64 A2y = ffma2(H4, Ua.y, ffma2(H2, Ub.y, ffma2(H0, Uc.y,
                        ffma2(G4, Va.y, ffma2(G2, Vb.y, fmul2(G0, Vc.y))))));
        const u64 A3x = ffma2(H5, Ua.x, ffma2(H3, Ub.x, ffma2(H1, Uc.x,
                        ffma2(G5, Va.x, ffma2(G3, Vb.x, fmul2(G1, Vc.x))))));
        const u64 A3y = ffma2(H5, Ua.y, ffma2(H3, Ub.y, ffma2(H1, Uc.y,
                        ffma2(G5, Va.y, ffma2(G3, Vb.y, fmul2(G1, Vc.y))))));

        // halo column pass (packed pairwise: lo = s-side, hi = d-side)
        const u64 P0 = pk(hsa, hua), Q0 = pk(hta, hva);
        const u64 P1 = pk(hsb, hub), Q1 = pk(htb, hvb);
        const u64 P2 = pk(hsc, huc), Q2 = pk(htc, hvc);
        const u64 B02 = ffma2(H4, P0, ffma2(H2, P1, ffma2(H0, P2,
                        ffma2(G4, Q0, ffma2(G2, Q1, fmul2(G0, Q2))))));   // (b0, b2)
        const u64 B13 = ffma2(H5, P0, ffma2(H3, P1, ffma2(H1, P2,
                        ffma2(G5, Q0, ffma2(G3, Q1, fmul2(G1, Q2))))));   // (b1, b3)

        // ---- roll window + load next row (consumed next iteration) ----
        Sa = Sb; Sb = Sc; Ta = Tb; Tb = Tc;
        Ua = Ub; Ub = Uc; Va = Vb; Vb = Vc;
        hsa = hsb; hsb = hsc; hta = htb; htb = htc;
        hua = hub; hub = huc; hva = hvb; hvb = hvc;
        if (i != RW - 1) {
            const int rn = reflH(r + 2);
            Sc = ldg4(pss, rn); Tc = ldg4(psd, rn);
            Uc = ldg4(pds, rn); Vc = ldg4(pdd, rn);
            hsc = ldg1(pss, rn, dq); htc = ldg1(psd, rn, dq);
            huc = ldg1(pds, rn, dq); hvc = ldg1(pdd, rn, dq);
        }

        // ---- row pass ----
        #pragma unroll
        for (int py = 0; py < 2; ++py) {
            const u64 Xa = py ? A1x : A0x, Xb = py ? A1y : A0y;   // sv: {x0,x1},{x2,x3}
            const u64 Ya = py ? A3x : A2x, Yb = py ? A3y : A2y;   // dv
            const u64 B  = py ? B13 : B02;
            const float hx = lof(B), hy = hif(B);

            // v[c-1]: from lane-1's x3; strip0 lane0 -> in-lane v[1], strip1 lane0 -> halo
            float xm1 = shup(hif(Xb)); if (lane == 0)  xm1 = strip ? hx : hif(Xa);
            // v[c+4]: from lane+1's x0; strip0 lane31 -> halo, strip1 lane31 -> in-lane v[254]
            float xp4 = shdn(lof(Xa)); if (lane == 31) xp4 = strip ? lof(Xb) : hx;
            float ym1 = shup(hif(Yb)); if (lane == 0)  ym1 = strip ? hy : hif(Ya);
            float yp4 = shdn(lof(Ya)); if (lane == 31) yp4 = strip ? lof(Yb) : hy;

            const u64 AX = pk(xm1, lof(Xa));        // {x-1, x0}
            const u64 MX = pk(hif(Xa), lof(Xb));    // {x1, x2}
            const u64 CX = pk(hif(Xb), xp4);        // {x3, x4}
            const u64 AY = pk(ym1, lof(Ya));
            const u64 MY = pk(hif(Ya), lof(Yb));
            const u64 CY = pk(hif(Yb), yp4);

            const u64 pe01 = ffma2(H4, AX, ffma2(H2, Xa, ffma2(H0, MX,
                             ffma2(G4, AY, ffma2(G2, Ya, fmul2(G0, MY))))));
            const u64 po01 = ffma2(H5, AX, ffma2(H3, Xa, ffma2(H1, MX,
                             ffma2(G5, AY, ffma2(G3, Ya, fmul2(G1, MY))))));
            const u64 pe23 = ffma2(H4, MX, ffma2(H2, Xb, ffma2(H0, CX,
                             ffma2(G4, MY, ffma2(G2, Yb, fmul2(G0, CY))))));
            const u64 po23 = ffma2(H5, MX, ffma2(H3, Xb, ffma2(H1, CX,
                             ffma2(G5, MY, ffma2(G3, Yb, fmul2(G1, CY))))));

            float e0, e1, f0, f1;
            float* __restrict__ prow = pout + (size_t)(2 * r + py) * (2 * WW);
            unpk(pe01, e0, e1); unpk(po01, f0, f1);
            __stcs((float4*)prow, make_float4(e0, f0, e1, f1));
            unpk(pe23, e0, e1); unpk(po23, f0, f1);
            __stcs((float4*)(prow + 4), make_float4(e0, f0, e1, f1));
        }
    }
}

extern "C" void kernel_launch(void* const* d_in, const int* in_sizes, int n_in,
                              void* d_out, int out_size) {
    const float* ss = (const float*)d_in[0];
    const float* sd = (const float*)d_in[1];
    const float* ds = (const float*)d_in[2];
    const float* dd = (const float*)d_in[3];
    const float* h  = (const float*)d_in[4];
    const float* g  = (const float*)d_in[5];
    float* out = (float*)d_out;

    dim3 grid(1, HH / RW, 4 * 64);   // (1, 4, 256) = 1024 blocks x 2 warps -> 1 wave
    idwt2d<<<grid, NT>>>(ss, sd, ds, dd, h, g, out);
}